// round 9
// baseline (speedup 1.0000x reference)
#include <cuda_runtime.h>
#include <cstdint>

#define IMG  224
#define HW   (IMG * IMG)        // 50176
#define WN   41                 // staged window extent (32 + 4 + 4 + 1), odd
#define PLANE (WN * WN)         // 1681 elements per plane
#define NT   512

// compile-time byte offsets
#define PAIR_S (PLANE * 8)      // 13448 : image stride in pair region
#define PAIR_R (16 * WN * 8)    // 5248  : 16-row step in pair region
#define SCAL_S (PLANE * 4)      // 6724
#define SCAL_R (16 * WN * 4)    // 2624
#define SRC_R  (16 * IMG * 4)   // 14336 : 16-row step in global

__device__ __forceinline__ uint32_t s2u(const void* p) {
    uint32_t a;
    asm("{ .reg .u64 t; cvta.to.shared.u64 t, %1; cvt.u32.u64 %0, t; }"
        : "=r"(a) : "l"(p));
    return a;
}

template<int DOFF, int SOFF>
__device__ __forceinline__ void cpa(uint32_t db, const float* sb) {
    asm volatile("cp.async.ca.shared.global [%0+%2], [%1+%3], 4;"
                 :: "r"(db), "l"(sb), "n"(DOFF), "n"(SOFF));
}

// one (image S, row-step RR, column-half H) staging step: ch0,ch1 -> pair, ch2 -> scal
template<int S, int RR, int H>
__device__ __forceinline__ void stage(uint32_t pb, uint32_t sb_, const float* g) {
    cpa<S * PAIR_S + RR * PAIR_R + H * 256 + 0, (0 * HW) * 4 + RR * SRC_R + H * 128>(pb, g);
    cpa<S * PAIR_S + RR * PAIR_R + H * 256 + 4, (1 * HW) * 4 + RR * SRC_R + H * 128>(pb, g);
    cpa<S * SCAL_S + RR * SCAL_R + H * 128,     (2 * HW) * 4 + RR * SRC_R + H * 128>(sb_, g);
}

__global__ __launch_bounds__(NT, 4) void vm_kernel(
    const float* __restrict__ im1, const float* __restrict__ im2,
    const float* __restrict__ C,   const float* __restrict__ M1,
    const float* __restrict__ M2,  float* __restrict__ out)
{
    __shared__ __align__(16) float2 pair[2 * PLANE];  // (ch0,ch1): 26896 B
    __shared__ float               scal[2 * PLANE];   // ch2:       13448 B

    const int tid = threadIdx.x;
    const int l   = tid & 31;            // lane: y within tile
    const int w   = tid >> 5;            // warp: x pair {X0+w, X0+w+16}
    const int X0 = blockIdx.x * 32;
    const int Y0 = blockIdx.y * 32;
    const int n  = blockIdx.z;

    const float* b1 = im1 + n * 3 * HW;
    const float* b2 = im2 + n * 3 * HW;

    // staged window fully inside the image (fallback handles tails exactly)
    const int sx0 = min(max(X0 - 4, 0), IMG - WN);
    const int sy0 = min(max(Y0 - 4, 0), IMG - WN);

    // ── async staging, all offsets immediate beyond three bases ──
    // warp w covers rows {w, w+16, w+32<WN}; lane l covers cols {l, 32+l<WN}.
    {
        const float* g1 = b1 + (sy0 + w) * IMG + sx0 + l;
        const float* g2 = b2 + (sy0 + w) * IMG + sx0 + l;
        const uint32_t pb  = s2u(pair) + (uint32_t)((w * WN + l) * 8);
        const uint32_t sb_ = s2u(scal) + (uint32_t)((w * WN + l) * 4);
        stage<0, 0, 0>(pb, sb_, g1);
        stage<0, 1, 0>(pb, sb_, g1);
        stage<1, 0, 0>(pb, sb_, g2);
        stage<1, 1, 0>(pb, sb_, g2);
        if (w < WN - 32) {               // rows 32..40
            stage<0, 2, 0>(pb, sb_, g1);
            stage<1, 2, 0>(pb, sb_, g2);
        }
        if (l < WN - 32) {               // cols 32..40
            stage<0, 0, 1>(pb, sb_, g1);
            stage<0, 1, 1>(pb, sb_, g1);
            stage<1, 0, 1>(pb, sb_, g2);
            stage<1, 1, 1>(pb, sb_, g2);
            if (w < WN - 32) {
                stage<0, 2, 1>(pb, sb_, g1);
                stage<1, 2, 1>(pb, sb_, g2);
            }
        }
    }
    asm volatile("cp.async.commit_group;");

    // ── coalesced C/M loads for both pixels (overlap staging latency) ──
    const int y  = Y0 + l;
    const int i0 = (X0 + w) * IMG + y;
    const int i1 = i0 + 16 * IMG;
    float Cxs[2], Cys[2], m1s[2], m2s[2];
    Cxs[0] = __ldg(C  + (n * 2) * HW + i0);
    Cys[0] = __ldg(C  + (n * 2 + 1) * HW + i0);
    m1s[0] = __ldg(M1 + n * HW + i0);
    m2s[0] = __ldg(M2 + n * HW + i0);
    Cxs[1] = __ldg(C  + (n * 2) * HW + i1);
    Cys[1] = __ldg(C  + (n * 2 + 1) * HW + i1);
    m1s[1] = __ldg(M1 + n * HW + i1);
    m2s[1] = __ldg(M2 + n * HW + i1);

    const float fyv  = (float)y;
    const float sx0f = (float)sx0, sy0f = (float)sy0;
    const float lox = sx0f, hix = (float)(sx0 + WN - 1);
    const float loy = sy0f, hiy = (float)(sy0 + WN - 1);

    asm volatile("cp.async.wait_group 0;");
    __syncthreads();

    float* outn = out + n * 3 * HW;

#pragma unroll
    for (int t = 0; t < 2; t++) {
        const float fxv = (float)(X0 + w + 16 * t);
        const float Cx = Cxs[t], Cy = Cys[t];
        const float m1v = m1s[t], m2v = m2s[t];

        float res[3];
#pragma unroll
        for (int s = 0; s < 2; s++) {
            const float px = s ? (fxv - Cx) : (fxv + Cx);
            const float py = s ? (fyv - Cy) : (fyv + Cy);

            float fx = floorf(px), cx = ceilf(px);
            float fy = floorf(py), cy = ceilf(py);
            float wfx = 1.0f - (px - fx);
            float wcx = 1.0f - (cx - px);
            float wfy = 1.0f - (py - fy);
            float wcy = 1.0f - (cy - py);
            float wff = wfx * wfy, wcf = wcx * wfy;
            float wfc = wfx * wcy, wcc = wcx * wcy;

            float v0, v1, v2;
            if (fx >= lox && cx <= hix && fy >= loy && cy <= hiy) {
                // window ⊂ image → taps in-image → reference's flat-index
                // truncate/clip is a no-op; exact float-domain indices (<2^24)
                float dcf  = cx - fx;                    // 0 or 1
                float drf  = cy - fy;                    // 0 or 1
                float t00f = fmaf(fy - sy0f, (float)WN, fx - sx0f);
                float t10f = fmaf(drf, (float)WN, t00f);
                int t00 = (int)t00f;
                int t01 = (int)(t00f + dcf);
                int t10 = (int)t10f;
                int t11 = (int)(t10f + dcf);

                const float2* pp = pair + s * PLANE;
                const float*  sp = scal + s * PLANE;
                float2 a00 = pp[t00];
                float2 a01 = pp[t01];
                float2 a10 = pp[t10];
                float2 a11 = pp[t11];
                float  c00 = sp[t00];
                float  c01 = sp[t01];
                float  c10 = sp[t10];
                float  c11 = sp[t11];

                v0 = wff * a00.x;
                v0 = fmaf(wcf, a01.x, v0);
                v0 = fmaf(wfc, a10.x, v0);
                v0 = fmaf(wcc, a11.x, v0);
                v1 = wff * a00.y;
                v1 = fmaf(wcf, a01.y, v1);
                v1 = fmaf(wfc, a10.y, v1);
                v1 = fmaf(wcc, a11.y, v1);
                v2 = wff * c00;
                v2 = fmaf(wcf, c01, v2);
                v2 = fmaf(wfc, c10, v2);
                v2 = fmaf(wcc, c11, v2);
            } else {
                // exact reference fallback: ind = clip(int32(nx+224*ny),0,HW-1)
                const float* gim = s ? b2 : b1;
                int iff = (int)(fx + 224.0f * fy);
                int icf = (int)(cx + 224.0f * fy);
                int ifc = (int)(fx + 224.0f * cy);
                int icc = (int)(cx + 224.0f * cy);
                iff = min(max(iff, 0), HW - 1);
                icf = min(max(icf, 0), HW - 1);
                ifc = min(max(ifc, 0), HW - 1);
                icc = min(max(icc, 0), HW - 1);
                float acc[3];
#pragma unroll
                for (int ch = 0; ch < 3; ch++) {
                    const float* p = gim + ch * HW;
                    float v = wff * __ldg(p + iff);
                    v = fmaf(wcf, __ldg(p + icf), v);
                    v = fmaf(wfc, __ldg(p + ifc), v);
                    v = fmaf(wcc, __ldg(p + icc), v);
                    acc[ch] = v;
                }
                v0 = acc[0]; v1 = acc[1]; v2 = acc[2];
            }
            if (s == 0) { res[0] = v0 * m1v; res[1] = v1 * m1v; res[2] = v2 * m1v; }
            else        { res[0] = fmaf(v0, m2v, res[0]);
                          res[1] = fmaf(v1, m2v, res[1]);
                          res[2] = fmaf(v2, m2v, res[2]); }
        }

        const int i = (t == 0) ? i0 : i1;
#pragma unroll
        for (int ch = 0; ch < 3; ch++)
            outn[ch * HW + i] = res[ch];
    }
}

extern "C" void kernel_launch(void* const* d_in, const int* in_sizes, int n_in,
                              void* d_out, int out_size)
{
    const float* im1 = (const float*)d_in[0];
    const float* im2 = (const float*)d_in[1];
    const float* C   = (const float*)d_in[2];
    const float* M1  = (const float*)d_in[3];
    const float* M2  = (const float*)d_in[4];
    float* out = (float*)d_out;

    dim3 block(NT, 1, 1);
    dim3 grid(7, 7, 64);   // 3136 blocks, 32x32 px each
    vm_kernel<<<grid, block>>>(im1, im2, C, M1, M2, out);
}

// round 10
// speedup vs baseline: 1.5554x; 1.5554x over previous
#include <cuda_runtime.h>
#include <cstdint>

#define IMG  224
#define HW   (IMG * IMG)        // 50176
#define XWU  27                 // staged window width in x
#define SW   29                 // smem row stride in ELEMENTS (odd -> conflict-free)
#define YH   43                 // staged window rows in y
#define PLANE (SW * YH)         // 1247 elements per plane
#define NT   512

__global__ __launch_bounds__(NT, 4) void vm_kernel(
    const float* __restrict__ im1, const float* __restrict__ im2,
    const float* __restrict__ C,   const float* __restrict__ M1,
    const float* __restrict__ M2,  float* __restrict__ out)
{
    __shared__ __align__(16) float2 pair[2 * PLANE];  // (ch0,ch1): 19952 B
    __shared__ float               scal[2 * PLANE];   // ch2:        9976 B

    const int tid = threadIdx.x;
    const int l   = tid & 31;             // lane: y within tile
    const int w   = tid >> 5;             // warp: x within tile
    const int X0 = blockIdx.x * 16;
    const int Y0 = blockIdx.y * 32;
    const int n  = blockIdx.z;

    // staged window fully inside the image (fallback handles tails exactly)
    const int sx0 = min(max(X0 - 5, 0), IMG - XWU);
    const int sy0 = min(max(Y0 - 5, 0), IMG - YH);

    const float* b1 = im1 + n * 3 * HW;
    const float* b2 = im2 + n * 3 * HW;

    // ── staging via LDG+STS (cheap LSU issue; no LDGSTS 8-cyc tax) ──
    // warp w stages rows {w, w+16, w+32<YH} of each plane; lanes 0..26 carry
    // one float each (consecutive -> coalesced global reads). Loads batched
    // 6-at-a-time for MLP while keeping register pressure < 32.
    if (l < XWU) {
        const int off0 = (sy0 + w) * IMG + sx0 + l;
#pragma unroll
        for (int s = 0; s < 2; s++) {
            const float* g = (s ? b2 : b1) + off0;
            float2* pp = pair + s * PLANE + w * SW + l;
            float*  ss = scal + s * PLANE + w * SW + l;
            float a0 = __ldg(g);
            float a1 = __ldg(g + HW);
            float a2 = __ldg(g + 2 * HW);
            float c0 = __ldg(g + 16 * IMG);
            float c1 = __ldg(g + HW + 16 * IMG);
            float c2 = __ldg(g + 2 * HW + 16 * IMG);
            pp[0] = make_float2(a0, a1);
            ss[0] = a2;
            pp[16 * SW] = make_float2(c0, c1);
            ss[16 * SW] = c2;
            if (w < YH - 32) {            // rows 32..42: warps 0..10
                float d0 = __ldg(g + 32 * IMG);
                float d1 = __ldg(g + HW + 32 * IMG);
                float d2 = __ldg(g + 2 * HW + 32 * IMG);
                pp[32 * SW] = make_float2(d0, d1);
                ss[32 * SW] = d2;
            }
        }
    }

    // ── coalesced direct I/O (lanes along y) — overlaps staging latency ──
    const int x = X0 + w;
    const int y = Y0 + l;
    const int i = x * IMG + y;

    float Cx  = __ldg(C  + (n * 2) * HW + i);
    float Cy  = __ldg(C  + (n * 2 + 1) * HW + i);
    float m1v = __ldg(M1 + n * HW + i);
    float m2v = __ldg(M2 + n * HW + i);

    const float fxv = (float)x, fyv = (float)y;
    const float sx0f = (float)sx0, sy0f = (float)sy0;
    const float lox = sx0f, hix = (float)(sx0 + XWU - 1);
    const float loy = sy0f, hiy = (float)(sy0 + YH - 1);

    float pxs[2], pys[2];
    pxs[0] = fxv + Cx; pys[0] = fyv + Cy;
    pxs[1] = fxv - Cx; pys[1] = fyv - Cy;

    __syncthreads();

    float res[3];
#pragma unroll
    for (int s = 0; s < 2; s++) {
        const float px = pxs[s], py = pys[s];

        float fx = floorf(px), cx = ceilf(px);
        float fy = floorf(py), cy = ceilf(py);
        float wfx = 1.0f - (px - fx);
        float wcx = 1.0f - (cx - px);
        float wfy = 1.0f - (py - fy);
        float wcy = 1.0f - (cy - py);
        float wff = wfx * wfy, wcf = wcx * wfy;
        float wfc = wfx * wcy, wcc = wcx * wcy;

        float v0, v1, v2;
        if (fx >= lox && cx <= hix && fy >= loy && cy <= hiy) {
            // window ⊂ image → taps in-image → reference's flat-index
            // truncate/clip is a no-op; exact float-domain indices (<2^24)
            float dcf  = cx - fx;                       // 0 or 1
            float drf  = cy - fy;                       // 0 or 1
            float t00f = fmaf(fy - sy0f, (float)SW, fx - sx0f);
            float t10f = fmaf(drf, (float)SW, t00f);
            int t00 = (int)t00f;
            int t01 = (int)(t00f + dcf);
            int t10 = (int)t10f;
            int t11 = (int)(t10f + dcf);

            const float2* pp = pair + s * PLANE;
            const float*  sp = scal + s * PLANE;
            float2 a00 = pp[t00];
            float2 a01 = pp[t01];
            float2 a10 = pp[t10];
            float2 a11 = pp[t11];
            float  c00 = sp[t00];
            float  c01 = sp[t01];
            float  c10 = sp[t10];
            float  c11 = sp[t11];

            v0 = wff * a00.x;
            v0 = fmaf(wcf, a01.x, v0);
            v0 = fmaf(wfc, a10.x, v0);
            v0 = fmaf(wcc, a11.x, v0);
            v1 = wff * a00.y;
            v1 = fmaf(wcf, a01.y, v1);
            v1 = fmaf(wfc, a10.y, v1);
            v1 = fmaf(wcc, a11.y, v1);
            v2 = wff * c00;
            v2 = fmaf(wcf, c01, v2);
            v2 = fmaf(wfc, c10, v2);
            v2 = fmaf(wcc, c11, v2);
        } else {
            // exact reference fallback: ind = clip(int32(nx + 224*ny), 0, HW-1)
            const float* gim = s ? b2 : b1;
            int iff = (int)(fx + 224.0f * fy);
            int icf = (int)(cx + 224.0f * fy);
            int ifc = (int)(fx + 224.0f * cy);
            int icc = (int)(cx + 224.0f * cy);
            iff = min(max(iff, 0), HW - 1);
            icf = min(max(icf, 0), HW - 1);
            ifc = min(max(ifc, 0), HW - 1);
            icc = min(max(icc, 0), HW - 1);
            float acc[3];
#pragma unroll
            for (int ch = 0; ch < 3; ch++) {
                const float* p = gim + ch * HW;
                float v = wff * __ldg(p + iff);
                v = fmaf(wcf, __ldg(p + icf), v);
                v = fmaf(wfc, __ldg(p + ifc), v);
                v = fmaf(wcc, __ldg(p + icc), v);
                acc[ch] = v;
            }
            v0 = acc[0]; v1 = acc[1]; v2 = acc[2];
        }
        if (s == 0) { res[0] = v0 * m1v; res[1] = v1 * m1v; res[2] = v2 * m1v; }
        else        { res[0] = fmaf(v0, m2v, res[0]);
                      res[1] = fmaf(v1, m2v, res[1]);
                      res[2] = fmaf(v2, m2v, res[2]); }
    }

    // ── direct coalesced stores (lanes along y) ──
    float* outn = out + n * 3 * HW;
#pragma unroll
    for (int ch = 0; ch < 3; ch++)
        outn[ch * HW + i] = res[ch];
}

extern "C" void kernel_launch(void* const* d_in, const int* in_sizes, int n_in,
                              void* d_out, int out_size)
{
    const float* im1 = (const float*)d_in[0];
    const float* im2 = (const float*)d_in[1];
    const float* C   = (const float*)d_in[2];
    const float* M1  = (const float*)d_in[3];
    const float* M2  = (const float*)d_in[4];
    float* out = (float*)d_out;

    dim3 block(NT, 1, 1);
    dim3 grid(14, 7, 64);   // 6272 blocks, 16x32 px each
    vm_kernel<<<grid, block>>>(im1, im2, C, M1, M2, out);
}

// round 11
// speedup vs baseline: 1.6693x; 1.0733x over previous
#include <cuda_runtime.h>
#include <cstdint>

#define IMG  224
#define HW   (IMG * IMG)        // 50176
#define WN   41                 // staged window extent (32+4+4+1), ODD stride
#define PLANE (WN * WN)         // 1681 elements per plane
#define NT   512

__global__ __launch_bounds__(NT, 4) void vm_kernel(
    const float* __restrict__ im1, const float* __restrict__ im2,
    const float* __restrict__ C,   const float* __restrict__ M1,
    const float* __restrict__ M2,  float* __restrict__ out)
{
    __shared__ __align__(16) float2 pair[2 * PLANE];  // (ch0,ch1): 26896 B
    __shared__ float               scal[2 * PLANE];   // ch2:       13448 B

    const int tid = threadIdx.x;
    const int l   = tid & 31;            // lane: y within tile
    const int w   = tid >> 5;            // warp: x pair {X0+w, X0+w+16}
    const int X0 = blockIdx.x * 32;
    const int Y0 = blockIdx.y * 32;
    const int n  = blockIdx.z;

    const float* b1 = im1 + n * 3 * HW;
    const float* b2 = im2 + n * 3 * HW;

    // staged window fully inside the image (fallback handles tails exactly)
    const int sx0 = min(max(X0 - 4, 0), IMG - WN);
    const int sy0 = min(max(Y0 - 4, 0), IMG - WN);

    // ── staging via LDG+STS, balanced linear site loop ──
    // site idx -> (r, c); smem index == idx (stride == row width == WN).
    // 1681 sites / 512 threads: 3-4 iterations, division-free increments.
    {
        int r = tid / WN;
        int c = tid - r * WN;
        const int DR = NT / WN;          // 12
        const int DC = NT - DR * WN;     // 20
        const float* g1base = b1 + sy0 * IMG + sx0;
        const float* g2base = b2 + sy0 * IMG + sx0;
#pragma unroll 4
        for (int idx = tid; idx < PLANE; idx += NT) {
            int g = r * IMG + c;
            float a0 = __ldg(g1base + g);
            float a1 = __ldg(g1base + HW + g);
            float a2 = __ldg(g1base + 2 * HW + g);
            float d0 = __ldg(g2base + g);
            float d1 = __ldg(g2base + HW + g);
            float d2 = __ldg(g2base + 2 * HW + g);
            pair[idx]         = make_float2(a0, a1);
            scal[idx]         = a2;
            pair[PLANE + idx] = make_float2(d0, d1);
            scal[PLANE + idx] = d2;
            r += DR; c += DC;
            if (c >= WN) { c -= WN; r += 1; }
        }
    }

    // ── coalesced C/M loads for both pixels (overlap staging latency) ──
    const int y  = Y0 + l;
    const int i0 = (X0 + w) * IMG + y;
    const int i1 = i0 + 16 * IMG;
    float Cxs[2], Cys[2], m1s[2], m2s[2];
    Cxs[0] = __ldg(C  + (n * 2) * HW + i0);
    Cys[0] = __ldg(C  + (n * 2 + 1) * HW + i0);
    m1s[0] = __ldg(M1 + n * HW + i0);
    m2s[0] = __ldg(M2 + n * HW + i0);
    Cxs[1] = __ldg(C  + (n * 2) * HW + i1);
    Cys[1] = __ldg(C  + (n * 2 + 1) * HW + i1);
    m1s[1] = __ldg(M1 + n * HW + i1);
    m2s[1] = __ldg(M2 + n * HW + i1);

    const float fyv  = (float)y;
    const float sx0f = (float)sx0, sy0f = (float)sy0;
    const float lox = sx0f, hix = (float)(sx0 + WN - 1);
    const float loy = sy0f, hiy = (float)(sy0 + WN - 1);

    __syncthreads();

    float* outn = out + n * 3 * HW;

#pragma unroll
    for (int t = 0; t < 2; t++) {
        const float fxv = (float)(X0 + w + 16 * t);
        const float Cx = Cxs[t], Cy = Cys[t];
        const float m1v = m1s[t], m2v = m2s[t];

        float res[3];
#pragma unroll
        for (int s = 0; s < 2; s++) {
            const float px = s ? (fxv - Cx) : (fxv + Cx);
            const float py = s ? (fyv - Cy) : (fyv + Cy);

            float fx = floorf(px), cx = ceilf(px);
            float fy = floorf(py), cy = ceilf(py);
            float wfx = 1.0f - (px - fx);
            float wcx = 1.0f - (cx - px);
            float wfy = 1.0f - (py - fy);
            float wcy = 1.0f - (cy - py);
            float wff = wfx * wfy, wcf = wcx * wfy;
            float wfc = wfx * wcy, wcc = wcx * wcy;

            float v0, v1, v2;
            if (fx >= lox && cx <= hix && fy >= loy && cy <= hiy) {
                // window ⊂ image → taps in-image → reference's flat-index
                // truncate/clip is a no-op; exact float-domain indices (<2^24)
                float dcf  = cx - fx;                    // 0 or 1
                float drf  = cy - fy;                    // 0 or 1
                float t00f = fmaf(fy - sy0f, (float)WN, fx - sx0f);
                float t10f = fmaf(drf, (float)WN, t00f);
                int t00 = (int)t00f;
                int t01 = (int)(t00f + dcf);
                int t10 = (int)t10f;
                int t11 = (int)(t10f + dcf);

                const float2* pp = pair + s * PLANE;
                const float*  sp = scal + s * PLANE;
                float2 a00 = pp[t00];
                float2 a01 = pp[t01];
                float2 a10 = pp[t10];
                float2 a11 = pp[t11];
                float  c00 = sp[t00];
                float  c01 = sp[t01];
                float  c10 = sp[t10];
                float  c11 = sp[t11];

                v0 = wff * a00.x;
                v0 = fmaf(wcf, a01.x, v0);
                v0 = fmaf(wfc, a10.x, v0);
                v0 = fmaf(wcc, a11.x, v0);
                v1 = wff * a00.y;
                v1 = fmaf(wcf, a01.y, v1);
                v1 = fmaf(wfc, a10.y, v1);
                v1 = fmaf(wcc, a11.y, v1);
                v2 = wff * c00;
                v2 = fmaf(wcf, c01, v2);
                v2 = fmaf(wfc, c10, v2);
                v2 = fmaf(wcc, c11, v2);
            } else {
                // exact reference fallback: ind = clip(int32(nx+224*ny),0,HW-1)
                const float* gim = s ? b2 : b1;
                int iff = (int)(fx + 224.0f * fy);
                int icf = (int)(cx + 224.0f * fy);
                int ifc = (int)(fx + 224.0f * cy);
                int icc = (int)(cx + 224.0f * cy);
                iff = min(max(iff, 0), HW - 1);
                icf = min(max(icf, 0), HW - 1);
                ifc = min(max(ifc, 0), HW - 1);
                icc = min(max(icc, 0), HW - 1);
                float acc[3];
#pragma unroll
                for (int ch = 0; ch < 3; ch++) {
                    const float* p = gim + ch * HW;
                    float v = wff * __ldg(p + iff);
                    v = fmaf(wcf, __ldg(p + icf), v);
                    v = fmaf(wfc, __ldg(p + ifc), v);
                    v = fmaf(wcc, __ldg(p + icc), v);
                    acc[ch] = v;
                }
                v0 = acc[0]; v1 = acc[1]; v2 = acc[2];
            }
            if (s == 0) { res[0] = v0 * m1v; res[1] = v1 * m1v; res[2] = v2 * m1v; }
            else        { res[0] = fmaf(v0, m2v, res[0]);
                          res[1] = fmaf(v1, m2v, res[1]);
                          res[2] = fmaf(v2, m2v, res[2]); }
        }

        const int i = (t == 0) ? i0 : i1;
#pragma unroll
        for (int ch = 0; ch < 3; ch++)
            outn[ch * HW + i] = res[ch];
    }
}

extern "C" void kernel_launch(void* const* d_in, const int* in_sizes, int n_in,
                              void* d_out, int out_size)
{
    const float* im1 = (const float*)d_in[0];
    const float* im2 = (const float*)d_in[1];
    const float* C   = (const float*)d_in[2];
    const float* M1  = (const float*)d_in[3];
    const float* M2  = (const float*)d_in[4];
    float* out = (float*)d_out;

    dim3 block(NT, 1, 1);
    dim3 grid(7, 7, 64);   // 3136 blocks, 32x32 px each
    vm_kernel<<<grid, block>>>(im1, im2, C, M1, M2, out);
}

// round 13
// speedup vs baseline: 1.9227x; 1.1518x over previous
#include <cuda_runtime.h>
#include <cuda_fp16.h>
#include <cstdint>

#define IMG 224
#define HW  (IMG * IMG)        // 50176
#define WN  41                 // staged window extent (32+4+4+1), ODD stride
#define PLANE (WN * WN)        // 1681 sites per plane
#define NT  512

// packed site: p01 = half2(ch0, ch1), p2x = half2(ch2, 0) — 8 bytes
struct __align__(8) Site {
    __half2 p01;
    __half2 p2x;
};

__global__ __launch_bounds__(NT, 4) void vm_kernel(
    const float* __restrict__ im1, const float* __restrict__ im2,
    const float* __restrict__ C,   const float* __restrict__ M1,
    const float* __restrict__ M2,  float* __restrict__ out)
{
    __shared__ __align__(16) Site rgb[2 * PLANE];   // 26896 B

    const int tid = threadIdx.x;
    const int l   = tid & 31;            // lane: y within tile
    const int w   = tid >> 5;            // warp: x pair {X0+w, X0+w+16}
    const int X0 = blockIdx.x * 32;
    const int Y0 = blockIdx.y * 32;
    const int n  = blockIdx.z;

    const float* b1 = im1 + n * 3 * HW;
    const float* b2 = im2 + n * 3 * HW;

    // staged window fully inside the image (fallback handles tails exactly)
    const int sx0 = min(max(X0 - 4, 0), IMG - WN);
    const int sy0 = min(max(Y0 - 4, 0), IMG - WN);

    // ── staging: LDG fp32 -> pack fp16x2 -> STS.64, balanced linear loop ──
    {
        int r = tid / WN;
        int c = tid - r * WN;
        const int DR = NT / WN;          // 12
        const int DC = NT - DR * WN;     // 20
        const float* g1base = b1 + sy0 * IMG + sx0;
        const float* g2base = b2 + sy0 * IMG + sx0;
#pragma unroll 4
        for (int idx = tid; idx < PLANE; idx += NT) {
            int g = r * IMG + c;
            float a0 = __ldg(g1base + g);
            float a1 = __ldg(g1base + HW + g);
            float a2 = __ldg(g1base + 2 * HW + g);
            float d0 = __ldg(g2base + g);
            float d1 = __ldg(g2base + HW + g);
            float d2 = __ldg(g2base + 2 * HW + g);
            Site s1, s2;
            s1.p01 = __floats2half2_rn(a0, a1);
            s1.p2x = __floats2half2_rn(a2, 0.0f);
            s2.p01 = __floats2half2_rn(d0, d1);
            s2.p2x = __floats2half2_rn(d2, 0.0f);
            rgb[idx]         = s1;
            rgb[PLANE + idx] = s2;
            r += DR; c += DC;
            if (c >= WN) { c -= WN; r += 1; }
        }
    }

    // ── coalesced C/M loads for both pixels (overlap staging latency) ──
    const int y  = Y0 + l;
    const int i0 = (X0 + w) * IMG + y;
    const int i1 = i0 + 16 * IMG;
    float Cxs[2], Cys[2], m1s[2], m2s[2];
    Cxs[0] = __ldg(C  + (n * 2) * HW + i0);
    Cys[0] = __ldg(C  + (n * 2 + 1) * HW + i0);
    m1s[0] = __ldg(M1 + n * HW + i0);
    m2s[0] = __ldg(M2 + n * HW + i0);
    Cxs[1] = __ldg(C  + (n * 2) * HW + i1);
    Cys[1] = __ldg(C  + (n * 2 + 1) * HW + i1);
    m1s[1] = __ldg(M1 + n * HW + i1);
    m2s[1] = __ldg(M2 + n * HW + i1);

    const float fyv  = (float)y;
    const float sx0f = (float)sx0, sy0f = (float)sy0;
    const float lox = sx0f, hix = (float)(sx0 + WN - 1);
    const float loy = sy0f, hiy = (float)(sy0 + WN - 1);

    __syncthreads();

    float* outn = out + n * 3 * HW;

#pragma unroll
    for (int t = 0; t < 2; t++) {
        const float fxv = (float)(X0 + w + 16 * t);
        const float Cx = Cxs[t], Cy = Cys[t];
        const float m1v = m1s[t], m2v = m2s[t];

        float res[3];
#pragma unroll
        for (int s = 0; s < 2; s++) {
            const float px = s ? (fxv - Cx) : (fxv + Cx);
            const float py = s ? (fyv - Cy) : (fyv + Cy);

            float fx = floorf(px), cx = ceilf(px);
            float fy = floorf(py), cy = ceilf(py);
            float wfx = 1.0f - (px - fx);
            float wcx = 1.0f - (cx - px);
            float wfy = 1.0f - (py - fy);
            float wcy = 1.0f - (cy - py);
            float wff = wfx * wfy, wcf = wcx * wfy;
            float wfc = wfx * wcy, wcc = wcx * wcy;

            float v0, v1, v2;
            if (fx >= lox && cx <= hix && fy >= loy && cy <= hiy) {
                // window ⊂ image → taps in-image → reference's flat-index
                // truncate/clip is a no-op; exact float-domain indices (<2^24)
                float dcf  = cx - fx;                    // 0 or 1
                float drf  = cy - fy;                    // 0 or 1
                float t00f = fmaf(fy - sy0f, (float)WN, fx - sx0f);
                float t10f = fmaf(drf, (float)WN, t00f);
                int t00 = (int)t00f;
                int t01 = (int)(t00f + dcf);
                int t10 = (int)t10f;
                int t11 = (int)(t10f + dcf);

                const Site* pp = rgb + s * PLANE;
                Site r00 = pp[t00];
                Site r01 = pp[t01];
                Site r10 = pp[t10];
                Site r11 = pp[t11];

                float2 a00 = __half22float2(r00.p01);
                float2 a01 = __half22float2(r01.p01);
                float2 a10 = __half22float2(r10.p01);
                float2 a11 = __half22float2(r11.p01);
                float  c00 = __low2float(r00.p2x);
                float  c01 = __low2float(r01.p2x);
                float  c10 = __low2float(r10.p2x);
                float  c11 = __low2float(r11.p2x);

                v0 = wff * a00.x;
                v0 = fmaf(wcf, a01.x, v0);
                v0 = fmaf(wfc, a10.x, v0);
                v0 = fmaf(wcc, a11.x, v0);
                v1 = wff * a00.y;
                v1 = fmaf(wcf, a01.y, v1);
                v1 = fmaf(wfc, a10.y, v1);
                v1 = fmaf(wcc, a11.y, v1);
                v2 = wff * c00;
                v2 = fmaf(wcf, c01, v2);
                v2 = fmaf(wfc, c10, v2);
                v2 = fmaf(wcc, c11, v2);
            } else {
                // exact fp32 reference fallback:
                // ind = clip(int32(nx + 224*ny), 0, HW-1)
                const float* gim = s ? b2 : b1;
                int iff = (int)(fx + 224.0f * fy);
                int icf = (int)(cx + 224.0f * fy);
                int ifc = (int)(fx + 224.0f * cy);
                int icc = (int)(cx + 224.0f * cy);
                iff = min(max(iff, 0), HW - 1);
                icf = min(max(icf, 0), HW - 1);
                ifc = min(max(ifc, 0), HW - 1);
                icc = min(max(icc, 0), HW - 1);
                float acc[3];
#pragma unroll
                for (int ch = 0; ch < 3; ch++) {
                    const float* p = gim + ch * HW;
                    float v = wff * __ldg(p + iff);
                    v = fmaf(wcf, __ldg(p + icf), v);
                    v = fmaf(wfc, __ldg(p + ifc), v);
                    v = fmaf(wcc, __ldg(p + icc), v);
                    acc[ch] = v;
                }
                v0 = acc[0]; v1 = acc[1]; v2 = acc[2];
            }
            if (s == 0) { res[0] = v0 * m1v; res[1] = v1 * m1v; res[2] = v2 * m1v; }
            else        { res[0] = fmaf(v0, m2v, res[0]);
                          res[1] = fmaf(v1, m2v, res[1]);
                          res[2] = fmaf(v2, m2v, res[2]); }
        }

        const int i = (t == 0) ? i0 : i1;
#pragma unroll
        for (int ch = 0; ch < 3; ch++)
            outn[ch * HW + i] = res[ch];
    }
}

extern "C" void kernel_launch(void* const* d_in, const int* in_sizes, int n_in,
                              void* d_out, int out_size)
{
    const float* im1 = (const float*)d_in[0];
    const float* im2 = (const float*)d_in[1];
    const float* C   = (const float*)d_in[2];
    const float* M1  = (const float*)d_in[3];
    const float* M2  = (const float*)d_in[4];
    float* out = (float*)d_out;

    dim3 block(NT, 1, 1);
    dim3 grid(7, 7, 64);   // 3136 blocks, 32x32 px each
    vm_kernel<<<grid, block>>>(im1, im2, C, M1, M2, out);
}

// round 14
// speedup vs baseline: 2.0096x; 1.0452x over previous
#include <cuda_runtime.h>
#include <cuda_fp16.h>
#include <cstdint>

#define IMG 224
#define HW  (IMG * IMG)        // 50176
#define WX  42                 // staged window width (even -> float2 loads)
#define SX  43                 // smem row stride in 8B slots (ODD -> bank-free)
#define YH  41                 // staged window rows (32+4+4+1)
#define PLANE (SX * YH)        // 1763 slots per image
#define NJ  (YH * (WX / 2))    // 861 two-site staging jobs
#define NT  512

// packed site: p01 = half2(ch0, ch1), p2x = half2(ch2, 0) — 8 bytes
struct __align__(8) Site {
    __half2 p01;
    __half2 p2x;
};

__global__ __launch_bounds__(NT, 4) void vm_kernel(
    const float* __restrict__ im1, const float* __restrict__ im2,
    const float* __restrict__ C,   const float* __restrict__ M1,
    const float* __restrict__ M2,  float* __restrict__ out)
{
    __shared__ __align__(16) Site rgb[2 * PLANE];   // 28208 B

    const int tid = threadIdx.x;
    const int l   = tid & 31;            // lane: y within tile
    const int w   = tid >> 5;            // warp: x pair {X0+w, X0+w+16}
    const int X0 = blockIdx.x * 32;
    const int Y0 = blockIdx.y * 32;
    const int n  = blockIdx.z;

    const float* b1 = im1 + n * 3 * HW;
    const float* b2 = im2 + n * 3 * HW;

    // staged window fully inside the image; sx0 EVEN in all cases
    // (X0-4 ≡ 28 mod 32, clamps 0 and IMG-WX=182 are even) -> 8B-aligned rows
    const int sx0 = min(max(X0 - 4, 0), IMG - WX);
    const int sy0 = min(max(Y0 - 4, 0), IMG - YH);

    // ── staging: float2 LDG -> fp16 pack -> 2x STS.64 per image, 861 jobs ──
    {
        const float* g1base = b1 + sy0 * IMG + sx0;
        const float* g2base = b2 + sy0 * IMG + sx0;
#pragma unroll
        for (int jj = 0; jj < 2; jj++) {
            int j = tid + jj * NT;
            if (j < NJ) {
                int r = j / 21;              // 21 float2 pairs per row
                int k = j - r * 21;
                int g = r * IMG + 2 * k;
                int si = r * SX + 2 * k;
                {
                    const float* G = g1base + g;
                    float2 a0 = __ldg((const float2*)(G));
                    float2 a1 = __ldg((const float2*)(G + HW));
                    float2 a2 = __ldg((const float2*)(G + 2 * HW));
                    Site sA, sB;
                    sA.p01 = __floats2half2_rn(a0.x, a1.x);
                    sA.p2x = __floats2half2_rn(a2.x, 0.0f);
                    sB.p01 = __floats2half2_rn(a0.y, a1.y);
                    sB.p2x = __floats2half2_rn(a2.y, 0.0f);
                    rgb[si]     = sA;
                    rgb[si + 1] = sB;
                }
                {
                    const float* G = g2base + g;
                    float2 a0 = __ldg((const float2*)(G));
                    float2 a1 = __ldg((const float2*)(G + HW));
                    float2 a2 = __ldg((const float2*)(G + 2 * HW));
                    Site sA, sB;
                    sA.p01 = __floats2half2_rn(a0.x, a1.x);
                    sA.p2x = __floats2half2_rn(a2.x, 0.0f);
                    sB.p01 = __floats2half2_rn(a0.y, a1.y);
                    sB.p2x = __floats2half2_rn(a2.y, 0.0f);
                    rgb[PLANE + si]     = sA;
                    rgb[PLANE + si + 1] = sB;
                }
            }
        }
    }

    // ── coalesced C/M loads for both pixels (overlap staging latency) ──
    const int y  = Y0 + l;
    const int i0 = (X0 + w) * IMG + y;
    const int i1 = i0 + 16 * IMG;
    float Cxs[2], Cys[2], m1s[2], m2s[2];
    Cxs[0] = __ldg(C  + (n * 2) * HW + i0);
    Cys[0] = __ldg(C  + (n * 2 + 1) * HW + i0);
    m1s[0] = __ldg(M1 + n * HW + i0);
    m2s[0] = __ldg(M2 + n * HW + i0);
    Cxs[1] = __ldg(C  + (n * 2) * HW + i1);
    Cys[1] = __ldg(C  + (n * 2 + 1) * HW + i1);
    m1s[1] = __ldg(M1 + n * HW + i1);
    m2s[1] = __ldg(M2 + n * HW + i1);

    const float fyv  = (float)y;
    const float sx0f = (float)sx0, sy0f = (float)sy0;
    const float lox = sx0f, hix = (float)(sx0 + WX - 1);
    const float loy = sy0f, hiy = (float)(sy0 + YH - 1);

    __syncthreads();

    float* outn = out + n * 3 * HW;

#pragma unroll
    for (int t = 0; t < 2; t++) {
        const float fxv = (float)(X0 + w + 16 * t);
        const float Cx = Cxs[t], Cy = Cys[t];
        const float m1v = m1s[t], m2v = m2s[t];

        float res[3];
#pragma unroll
        for (int s = 0; s < 2; s++) {
            const float px = s ? (fxv - Cx) : (fxv + Cx);
            const float py = s ? (fyv - Cy) : (fyv + Cy);

            float fx = floorf(px), cx = ceilf(px);
            float fy = floorf(py), cy = ceilf(py);
            float wfx = 1.0f - (px - fx);
            float wcx = 1.0f - (cx - px);
            float wfy = 1.0f - (py - fy);
            float wcy = 1.0f - (cy - py);
            float wff = wfx * wfy, wcf = wcx * wfy;
            float wfc = wfx * wcy, wcc = wcx * wcy;

            float v0, v1, v2;
            if (fx >= lox && cx <= hix && fy >= loy && cy <= hiy) {
                // window ⊂ image → taps in-image → reference's flat-index
                // truncate/clip is a no-op; exact float-domain indices (<2^24)
                float dcf  = cx - fx;                    // 0 or 1
                float drf  = cy - fy;                    // 0 or 1
                float t00f = fmaf(fy - sy0f, (float)SX, fx - sx0f);
                float t10f = fmaf(drf, (float)SX, t00f);
                int t00 = (int)t00f;
                int t01 = (int)(t00f + dcf);
                int t10 = (int)t10f;
                int t11 = (int)(t10f + dcf);

                const Site* pp = rgb + s * PLANE;
                Site r00 = pp[t00];
                Site r01 = pp[t01];
                Site r10 = pp[t10];
                Site r11 = pp[t11];

                float2 a00 = __half22float2(r00.p01);
                float2 a01 = __half22float2(r01.p01);
                float2 a10 = __half22float2(r10.p01);
                float2 a11 = __half22float2(r11.p01);
                float  c00 = __low2float(r00.p2x);
                float  c01 = __low2float(r01.p2x);
                float  c10 = __low2float(r10.p2x);
                float  c11 = __low2float(r11.p2x);

                v0 = wff * a00.x;
                v0 = fmaf(wcf, a01.x, v0);
                v0 = fmaf(wfc, a10.x, v0);
                v0 = fmaf(wcc, a11.x, v0);
                v1 = wff * a00.y;
                v1 = fmaf(wcf, a01.y, v1);
                v1 = fmaf(wfc, a10.y, v1);
                v1 = fmaf(wcc, a11.y, v1);
                v2 = wff * c00;
                v2 = fmaf(wcf, c01, v2);
                v2 = fmaf(wfc, c10, v2);
                v2 = fmaf(wcc, c11, v2);
            } else {
                // exact fp32 reference fallback:
                // ind = clip(int32(nx + 224*ny), 0, HW-1)
                const float* gim = s ? b2 : b1;
                int iff = (int)(fx + 224.0f * fy);
                int icf = (int)(cx + 224.0f * fy);
                int ifc = (int)(fx + 224.0f * cy);
                int icc = (int)(cx + 224.0f * cy);
                iff = min(max(iff, 0), HW - 1);
                icf = min(max(icf, 0), HW - 1);
                ifc = min(max(ifc, 0), HW - 1);
                icc = min(max(icc, 0), HW - 1);
                float acc[3];
#pragma unroll
                for (int ch = 0; ch < 3; ch++) {
                    const float* p = gim + ch * HW;
                    float v = wff * __ldg(p + iff);
                    v = fmaf(wcf, __ldg(p + icf), v);
                    v = fmaf(wfc, __ldg(p + ifc), v);
                    v = fmaf(wcc, __ldg(p + icc), v);
                    acc[ch] = v;
                }
                v0 = acc[0]; v1 = acc[1]; v2 = acc[2];
            }
            if (s == 0) { res[0] = v0 * m1v; res[1] = v1 * m1v; res[2] = v2 * m1v; }
            else        { res[0] = fmaf(v0, m2v, res[0]);
                          res[1] = fmaf(v1, m2v, res[1]);
                          res[2] = fmaf(v2, m2v, res[2]); }
        }

        const int i = (t == 0) ? i0 : i1;
#pragma unroll
        for (int ch = 0; ch < 3; ch++)
            outn[ch * HW + i] = res[ch];
    }
}

extern "C" void kernel_launch(void* const* d_in, const int* in_sizes, int n_in,
                              void* d_out, int out_size)
{
    const float* im1 = (const float*)d_in[0];
    const float* im2 = (const float*)d_in[1];
    const float* C   = (const float*)d_in[2];
    const float* M1  = (const float*)d_in[3];
    const float* M2  = (const float*)d_in[4];
    float* out = (float*)d_out;

    dim3 block(NT, 1, 1);
    dim3 grid(7, 7, 64);   // 3136 blocks, 32x32 px each
    vm_kernel<<<grid, block>>>(im1, im2, C, M1, M2, out);
}